// round 1
// baseline (speedup 1.0000x reference)
#include <cuda_runtime.h>

#define NN 50000
#define EE 1600000
#define DD 128
#define GG 64
#define LL 3

// ---------------- scratch (static device globals; no allocation) ----------------
__device__ float g_bufA[NN * DD];   // ping-pong node features
__device__ float g_bufB[NN * DD];
__device__ float g_Sd[NN * DD];     // per-node sum of X[src] over data edges
__device__ float g_Sc[NN * DD];     // per-node sum of X[src] over ctrl edges
__device__ int   g_cntd[NN];
__device__ int   g_cntc[NN];
__device__ int   g_rowptr[NN + 1];
__device__ int   g_cursor[NN];
__device__ unsigned int g_edge[EE]; // src | (type<<31), sorted by dst

// ---------------- f32x2 packed helpers ----------------
__device__ __forceinline__ unsigned long long ffma2(unsigned long long a,
                                                    unsigned long long b,
                                                    unsigned long long c) {
    unsigned long long d;
    asm("fma.rn.f32x2 %0, %1, %2, %3;" : "=l"(d) : "l"(a), "l"(b), "l"(c));
    return d;
}
__device__ __forceinline__ unsigned long long pk2(float v) {
    unsigned long long d;
    unsigned int u = __float_as_uint(v);
    asm("mov.b64 %0, {%1, %2};" : "=l"(d) : "r"(u), "r"(u));
    return d;
}

// ---------------- CSR build ----------------
__global__ void k_zero_counts() {
    int i = blockIdx.x * blockDim.x + threadIdx.x;
    if (i < NN) { g_cntd[i] = 0; g_cntc[i] = 0; }
}

__global__ void k_count(const int* __restrict__ dst, const int* __restrict__ et) {
    int e = blockIdx.x * blockDim.x + threadIdx.x;
    if (e < EE) {
        int d = dst[e];
        if (et[e] == 0) atomicAdd(&g_cntd[d], 1);
        else            atomicAdd(&g_cntc[d], 1);
    }
}

// single-block exclusive scan over degrees -> rowptr (+ cursor copy)
__global__ void __launch_bounds__(1024) k_scan() {
    __shared__ int warp_sums[32];
    __shared__ int s_carry;
    int tid = threadIdx.x;
    int lane = tid & 31, wid = tid >> 5;
    if (tid == 0) s_carry = 0;
    __syncthreads();
    for (int base = 0; base < NN; base += 1024) {
        int i = base + tid;
        int v = (i < NN) ? (g_cntd[i] + g_cntc[i]) : 0;
        int x = v;
        #pragma unroll
        for (int off = 1; off < 32; off <<= 1) {
            int y = __shfl_up_sync(0xffffffffu, x, off);
            if (lane >= off) x += y;
        }
        if (lane == 31) warp_sums[wid] = x;
        __syncthreads();
        if (tid < 32) {
            int w = warp_sums[tid];
            #pragma unroll
            for (int off = 1; off < 32; off <<= 1) {
                int y = __shfl_up_sync(0xffffffffu, w, off);
                if (tid >= off) w += y;
            }
            warp_sums[tid] = w; // inclusive over warps
        }
        __syncthreads();
        int woff = (wid > 0) ? warp_sums[wid - 1] : 0;
        int incl = x + woff;
        if (i < NN) {
            int rp = s_carry + incl - v;
            g_rowptr[i] = rp;
            g_cursor[i] = rp;
        }
        int total = warp_sums[31];
        __syncthreads();
        if (tid == 0) s_carry += total;
        __syncthreads();
    }
    if (tid == 0) g_rowptr[NN] = s_carry;
}

__global__ void k_fill(const int* __restrict__ src, const int* __restrict__ dst,
                       const int* __restrict__ et) {
    int e = blockIdx.x * blockDim.x + threadIdx.x;
    if (e < EE) {
        int d = dst[e];
        int pos = atomicAdd(&g_cursor[d], 1);
        g_edge[pos] = (unsigned int)src[e] | ((unsigned int)et[e] << 31);
    }
}

// ---------------- edge aggregation: warp per dst node ----------------
__global__ void __launch_bounds__(256) k_aggregate(const float* __restrict__ X) {
    int w = (blockIdx.x * blockDim.x + threadIdx.x) >> 5;
    int lane = threadIdx.x & 31;
    if (w >= NN) return;
    int beg = g_rowptr[w], end = g_rowptr[w + 1];
    const float4* X4 = (const float4*)X;
    float4 ad = make_float4(0.f, 0.f, 0.f, 0.f);
    float4 ac = make_float4(0.f, 0.f, 0.f, 0.f);
    int j = beg;
    for (; j + 1 < end; j += 2) {
        unsigned int e0 = g_edge[j];
        unsigned int e1 = g_edge[j + 1];
        float4 v0 = __ldg(X4 + (int)(e0 & 0x7fffffffu) * 32 + lane);
        float4 v1 = __ldg(X4 + (int)(e1 & 0x7fffffffu) * 32 + lane);
        if (e0 >> 31) { ac.x += v0.x; ac.y += v0.y; ac.z += v0.z; ac.w += v0.w; }
        else          { ad.x += v0.x; ad.y += v0.y; ad.z += v0.z; ad.w += v0.w; }
        if (e1 >> 31) { ac.x += v1.x; ac.y += v1.y; ac.z += v1.z; ac.w += v1.w; }
        else          { ad.x += v1.x; ad.y += v1.y; ad.z += v1.z; ad.w += v1.w; }
    }
    if (j < end) {
        unsigned int e0 = g_edge[j];
        float4 v0 = __ldg(X4 + (int)(e0 & 0x7fffffffu) * 32 + lane);
        if (e0 >> 31) { ac.x += v0.x; ac.y += v0.y; ac.z += v0.z; ac.w += v0.w; }
        else          { ad.x += v0.x; ad.y += v0.y; ad.z += v0.z; ad.w += v0.w; }
    }
    ((float4*)g_Sd)[w * 32 + lane] = ad;
    ((float4*)g_Sc)[w * 32 + lane] = ac;
}

// ---------------- fused triple GEMM + bias + relu ----------------
// X' = relu(Sd@Wd + Sc@Wc + X@Ws + cntd*bd + cntc*bc + bs)
// block: 256 threads, 32 rows x 128 cols. thread (tx,ty): cols tx*4..+4, rows ty*4..+4
__global__ void __launch_bounds__(256) k_gemm(
    const float* __restrict__ Xin,
    const float* __restrict__ Wd, const float* __restrict__ bd,
    const float* __restrict__ Wc, const float* __restrict__ bc,
    const float* __restrict__ Ws, const float* __restrict__ bs,
    float* __restrict__ Y)
{
    __shared__ __align__(16) float sX[3][DD][32]; // [mat][k][row] transposed tiles, 48KB
    int tid = threadIdx.x;
    int rowbase = blockIdx.x * 32;

    // load tiles (transposed: k-major so main loop can LDS.64 row pairs)
    {
        int r = tid & 31;
        int kq = tid >> 5; // 0..7, covers 16 k each
        int row = rowbase + r;
        const float* srcs[3] = { g_Sd, g_Sc, Xin };
        #pragma unroll
        for (int m = 0; m < 3; m++) {
            #pragma unroll
            for (int q = 0; q < 4; q++) {
                float4 a;
                if (row < NN) a = __ldg((const float4*)(srcs[m] + row * DD) + kq * 4 + q);
                else          a = make_float4(0.f, 0.f, 0.f, 0.f);
                int k0 = kq * 16 + q * 4;
                sX[m][k0 + 0][r] = a.x;
                sX[m][k0 + 1][r] = a.y;
                sX[m][k0 + 2][r] = a.z;
                sX[m][k0 + 3][r] = a.w;
            }
        }
    }
    __syncthreads();

    int tx = tid & 31;
    int ty = tid >> 5;
    const float4* W4[3] = { (const float4*)Wd, (const float4*)Wc, (const float4*)Ws };
    unsigned long long acc[2][4] = { {0ull,0ull,0ull,0ull}, {0ull,0ull,0ull,0ull} };

    #pragma unroll 4
    for (int k = 0; k < DD; k++) {
        #pragma unroll
        for (int m = 0; m < 3; m++) {
            float4 wv = __ldg(W4[m] + k * 32 + tx);
            unsigned long long w0 = pk2(wv.x), w1 = pk2(wv.y);
            unsigned long long w2 = pk2(wv.z), w3 = pk2(wv.w);
            const unsigned long long* xp =
                (const unsigned long long*)&sX[m][k][0];
            unsigned long long xa = xp[ty * 2];     // rows (ty*4, ty*4+1)
            unsigned long long xb = xp[ty * 2 + 1]; // rows (ty*4+2, ty*4+3)
            acc[0][0] = ffma2(xa, w0, acc[0][0]);
            acc[0][1] = ffma2(xa, w1, acc[0][1]);
            acc[0][2] = ffma2(xa, w2, acc[0][2]);
            acc[0][3] = ffma2(xa, w3, acc[0][3]);
            acc[1][0] = ffma2(xb, w0, acc[1][0]);
            acc[1][1] = ffma2(xb, w1, acc[1][1]);
            acc[1][2] = ffma2(xb, w2, acc[1][2]);
            acc[1][3] = ffma2(xb, w3, acc[1][3]);
        }
    }

    float4 bdv = __ldg((const float4*)bd + tx);
    float4 bcv = __ldg((const float4*)bc + tx);
    float4 bsv = __ldg((const float4*)bs + tx);
    #pragma unroll
    for (int j = 0; j < 4; j++) {
        int row = rowbase + ty * 4 + j;
        if (row >= NN) continue;
        int p = j >> 1, h = j & 1;
        float2 c0 = *(float2*)&acc[p][0];
        float2 c1 = *(float2*)&acc[p][1];
        float2 c2 = *(float2*)&acc[p][2];
        float2 c3 = *(float2*)&acc[p][3];
        float4 o;
        o.x = h ? c0.y : c0.x;
        o.y = h ? c1.y : c1.x;
        o.z = h ? c2.y : c2.x;
        o.w = h ? c3.y : c3.x;
        float cd = (float)g_cntd[row];
        float cc = (float)g_cntc[row];
        o.x = fmaxf(fmaf(cd, bdv.x, fmaf(cc, bcv.x, o.x + bsv.x)), 0.f);
        o.y = fmaxf(fmaf(cd, bdv.y, fmaf(cc, bcv.y, o.y + bsv.y)), 0.f);
        o.z = fmaxf(fmaf(cd, bdv.z, fmaf(cc, bcv.z, o.z + bsv.z)), 0.f);
        o.w = fmaxf(fmaf(cd, bdv.w, fmaf(cc, bcv.w, o.w + bsv.w)), 0.f);
        ((float4*)Y)[row * 32 + tx] = o;
    }
}

// ---------------- mean pool per graph (batch_ids sorted) ----------------
__global__ void __launch_bounds__(DD) k_pool(const float* __restrict__ X,
                                             const int* __restrict__ batch,
                                             float* __restrict__ out) {
    int g = blockIdx.x;
    int c = threadIdx.x;
    // lower_bound(g)
    int lo = 0, hi = NN;
    while (lo < hi) { int m = (lo + hi) >> 1; if (batch[m] < g) lo = m + 1; else hi = m; }
    int start = lo;
    lo = start; hi = NN;
    while (lo < hi) { int m = (lo + hi) >> 1; if (batch[m] < g + 1) lo = m + 1; else hi = m; }
    int end = lo;

    float s0 = 0.f, s1 = 0.f, s2 = 0.f, s3 = 0.f;
    int n = start;
    for (; n + 3 < end; n += 4) {
        s0 += X[(n + 0) * DD + c];
        s1 += X[(n + 1) * DD + c];
        s2 += X[(n + 2) * DD + c];
        s3 += X[(n + 3) * DD + c];
    }
    for (; n < end; n++) s0 += X[n * DD + c];
    float s = (s0 + s1) + (s2 + s3);
    float cnt = (float)(end - start);
    out[g * DD + c] = s / fmaxf(cnt, 1.0f);
}

// ---------------- launch ----------------
extern "C" void kernel_launch(void* const* d_in, const int* in_sizes, int n_in,
                              void* d_out, int out_size) {
    const float* X  = (const float*)d_in[0];
    const float* Wd = (const float*)d_in[1];
    const float* bd = (const float*)d_in[2];
    const float* Wc = (const float*)d_in[3];
    const float* bc = (const float*)d_in[4];
    const float* Ws = (const float*)d_in[5];
    const float* bs = (const float*)d_in[6];
    const int* ei   = (const int*)d_in[7];
    const int* et   = (const int*)d_in[8];
    const int* bid  = (const int*)d_in[9];
    const int* srcp = ei;
    const int* dstp = ei + EE;

    void* pA = nullptr;
    void* pB = nullptr;
    cudaGetSymbolAddress(&pA, g_bufA);
    cudaGetSymbolAddress(&pB, g_bufB);
    float* A = (float*)pA;
    float* B = (float*)pB;

    // CSR build (graph identical across layers -> built once per call)
    k_zero_counts<<<(NN + 255) / 256, 256>>>();
    k_count<<<(EE + 255) / 256, 256>>>(dstp, et);
    k_scan<<<1, 1024>>>();
    k_fill<<<(EE + 255) / 256, 256>>>(srcp, dstp, et);

    const float* cur = X;
    float* outs[3] = { A, B, A };
    for (int l = 0; l < LL; l++) {
        k_aggregate<<<(NN * 32 + 255) / 256, 256>>>(cur);
        k_gemm<<<(NN + 31) / 32, 256>>>(cur,
                                        Wd + l * DD * DD, bd + l * DD,
                                        Wc + l * DD * DD, bc + l * DD,
                                        Ws + l * DD * DD, bs + l * DD,
                                        outs[l]);
        cur = outs[l];
    }
    k_pool<<<GG, DD>>>(cur, bid, (float*)d_out);
}